// round 2
// baseline (speedup 1.0000x reference)
#include <cuda_runtime.h>
#include <math.h>

#define S4     4
#define D4     1024
#define KDIM   4096      // S*D
#define RROWS  24        // 16 res + 4 pre + 4 post
#define MAXNT  8192      // B*T

// -------- scratch (no cudaMalloc allowed) --------
__device__ float g_wg  [RROWS * KDIM];   // w * (1+gamma), row-major [r][k]
__device__ float g_dots[MAXNT * RROWS];  // raw dots per token
__device__ float g_ssq [MAXNT];          // sum of squares per token
__device__ float g_H   [MAXNT * RROWS];  // Hres[16], Hpre[4], Hpost[4]

typedef unsigned long long u64;

__device__ __forceinline__ u64 fma2(u64 a, u64 b, u64 c) {
    u64 d;
    asm("fma.rn.f32x2 %0, %1, %2, %3;" : "=l"(d) : "l"(a), "l"(b), "l"(c));
    return d;
}
__device__ __forceinline__ float f2sum(u64 a) {
    float lo, hi;
    asm("mov.b64 {%0,%1}, %2;" : "=f"(lo), "=f"(hi) : "l"(a));
    return lo + hi;
}

// ============================================================
// K0: fold gamma into concatenated weight matrix
// ============================================================
__global__ void prep_kernel(const float* __restrict__ w_res,
                            const float* __restrict__ w_pre,
                            const float* __restrict__ w_post,
                            const float* __restrict__ gamma) {
    int idx = blockIdx.x * blockDim.x + threadIdx.x;
    if (idx >= RROWS * KDIM) return;
    int r = idx >> 12;          // / 4096
    int k = idx & (KDIM - 1);
    float w;
    if (r < 16)      w = w_res [r * KDIM + k];
    else if (r < 20) w = w_pre [(r - 16) * KDIM + k];
    else             w = w_post[(r - 20) * KDIM + k];
    g_wg[idx] = w * (1.0f + gamma[k]);
}

// ============================================================
// K1: per-token sumsq + 24 raw dots.
// Block = 16 tokens, 256 threads (8 warps).
// warp-pair handles 4 tokens; half 0 -> rows 0..11, half 1 -> rows 12..23.
// w chunk (24x512 fp32 = 48KB) staged in static smem; each w float4 LDS
// is reused across 4 tokens held in registers. FFMA2 everywhere.
// ============================================================
__global__ void __launch_bounds__(256, 1)
dots_kernel(const float* __restrict__ x) {
    __shared__ __align__(16) float sw[RROWS * 512];

    const int lane = threadIdx.x & 31;
    const int warp = threadIdx.x >> 5;
    const int pair = warp >> 1;        // 0..3
    const int half = warp & 1;         // 0 or 1 (row split)
    const int tok0 = blockIdx.x * 16 + pair * 4;
    const float* xb = x + (size_t)tok0 * KDIM;

    u64 acc[12][4];
#pragma unroll
    for (int r = 0; r < 12; ++r)
#pragma unroll
        for (int t = 0; t < 4; ++t) acc[r][t] = 0ull;
    u64 ssq[4] = {0ull, 0ull, 0ull, 0ull};

    longlong2 xv[4], xn[4];
    {   // prefetch gi = 0
        int k = lane * 4;
#pragma unroll
        for (int t = 0; t < 4; ++t)
            xv[t] = *(const longlong2*)(xb + t * KDIM + k);
    }

    for (int c = 0; c < 8; ++c) {                // 8 chunks of 512 k
        __syncthreads();
        // cooperative stage of wg chunk: 24*512 floats = 3072 float4
#pragma unroll
        for (int j = 0; j < 12; ++j) {
            int i   = threadIdx.x + 256 * j;     // float4 index
            int r   = i >> 7;                    // / 128
            int kk4 = i & 127;
            ((float4*)sw)[i] =
                *(const float4*)(g_wg + r * KDIM + c * 512 + kk4 * 4);
        }
        __syncthreads();

#pragma unroll
        for (int it = 0; it < 4; ++it) {
            int gi = c * 4 + it;                 // global 128-wide step
            if (gi < 31) {                       // prefetch next x tile
                int kn = (gi + 1) * 128 + lane * 4;
#pragma unroll
                for (int t = 0; t < 4; ++t)
                    xn[t] = *(const longlong2*)(xb + t * KDIM + kn);
            }
            if (half == 0) {
#pragma unroll
                for (int t = 0; t < 4; ++t) {
                    ssq[t] = fma2((u64)xv[t].x, (u64)xv[t].x, ssq[t]);
                    ssq[t] = fma2((u64)xv[t].y, (u64)xv[t].y, ssq[t]);
                }
            }
            const float* swb = sw + (half * 12) * 512 + it * 128 + lane * 4;
#pragma unroll
            for (int r = 0; r < 12; ++r) {
                longlong2 wv = *(const longlong2*)(swb + r * 512);
#pragma unroll
                for (int t = 0; t < 4; ++t) {
                    acc[r][t] = fma2((u64)wv.x, (u64)xv[t].x, acc[r][t]);
                    acc[r][t] = fma2((u64)wv.y, (u64)xv[t].y, acc[r][t]);
                }
            }
#pragma unroll
            for (int t = 0; t < 4; ++t) xv[t] = xn[t];
        }
    }

    // reduce + write
#pragma unroll
    for (int r = 0; r < 12; ++r) {
#pragma unroll
        for (int t = 0; t < 4; ++t) {
            float v = f2sum(acc[r][t]);
            v += __shfl_down_sync(0xffffffffu, v, 16);
            v += __shfl_down_sync(0xffffffffu, v, 8);
            v += __shfl_down_sync(0xffffffffu, v, 4);
            v += __shfl_down_sync(0xffffffffu, v, 2);
            v += __shfl_down_sync(0xffffffffu, v, 1);
            if (lane == 0)
                g_dots[(size_t)(tok0 + t) * RROWS + half * 12 + r] = v;
        }
    }
    if (half == 0) {
#pragma unroll
        for (int t = 0; t < 4; ++t) {
            float v = f2sum(ssq[t]);
            v += __shfl_down_sync(0xffffffffu, v, 16);
            v += __shfl_down_sync(0xffffffffu, v, 8);
            v += __shfl_down_sync(0xffffffffu, v, 4);
            v += __shfl_down_sync(0xffffffffu, v, 2);
            v += __shfl_down_sync(0xffffffffu, v, 1);
            if (lane == 0) g_ssq[tok0 + t] = v;
        }
    }
}

// ============================================================
// K2: per-token heads (sinkhorn + softmax + sigmoid)
// ============================================================
__device__ __forceinline__ float lse4(float a, float b, float c, float d) {
    float m = fmaxf(fmaxf(a, b), fmaxf(c, d));
    float s = expf(a - m) + expf(b - m) + expf(c - m) + expf(d - m);
    return m + logf(s);
}

__global__ void heads_kernel(const float* __restrict__ beta_res,
                             const float* __restrict__ beta_pre,
                             const float* __restrict__ beta_post,
                             const float* __restrict__ alpha_res,
                             const float* __restrict__ alpha_pre,
                             const float* __restrict__ alpha_post,
                             int nt) {
    int tok = blockIdx.x * blockDim.x + threadIdx.x;
    if (tok >= nt) return;

    float rstd = 64.0f / fmaxf(sqrtf(g_ssq[tok]), 1e-12f);
    const float* dp = g_dots + (size_t)tok * RROWS;
    float ar = alpha_res[0]  * rstd;
    float ap = alpha_pre[0]  * rstd;
    float ao = alpha_post[0] * rstd;

    float Z[16];
#pragma unroll
    for (int e = 0; e < 16; ++e)
        Z[e] = (beta_res[e] + ar * dp[e]) * 20.0f;   // / tau, tau = 0.05

    float u[4] = {0.f, 0.f, 0.f, 0.f};
    float v[4] = {0.f, 0.f, 0.f, 0.f};
#pragma unroll 1
    for (int itn = 0; itn < 10; ++itn) {
#pragma unroll
        for (int i = 0; i < 4; ++i)
            u[i] = -lse4(Z[i*4+0] + v[0], Z[i*4+1] + v[1],
                         Z[i*4+2] + v[2], Z[i*4+3] + v[3]);
#pragma unroll
        for (int j = 0; j < 4; ++j)
            v[j] = -lse4(Z[0*4+j] + u[0], Z[1*4+j] + u[1],
                         Z[2*4+j] + u[2], Z[3*4+j] + u[3]);
    }

    float* hp = g_H + (size_t)tok * RROWS;
#pragma unroll
    for (int i = 0; i < 4; ++i)
#pragma unroll
        for (int j = 0; j < 4; ++j)
            hp[i*4+j] = expf(Z[i*4+j] + u[i] + v[j]);

    // H_pre = softmax
    float p[4];
#pragma unroll
    for (int s = 0; s < 4; ++s) p[s] = beta_pre[s] + ap * dp[16 + s];
    float m = fmaxf(fmaxf(p[0], p[1]), fmaxf(p[2], p[3]));
    float e0 = expf(p[0]-m), e1 = expf(p[1]-m), e2 = expf(p[2]-m), e3 = expf(p[3]-m);
    float inv = 1.0f / (e0 + e1 + e2 + e3);
    hp[16] = e0*inv; hp[17] = e1*inv; hp[18] = e2*inv; hp[19] = e3*inv;

    // H_post = 2*sigmoid
#pragma unroll
    for (int s = 0; s < 4; ++s) {
        float q = beta_post[s] + ao * dp[20 + s];
        hp[20 + s] = 2.0f / (1.0f + expf(-q));
    }
}

// ============================================================
// K3: out[i,d] = sum_j Hres[i][j] x[j,d] + Hpost[i] * sum_s Hpre[s] x[s,d]
// one block per token, 256 threads, float4 per thread (D=1024)
// ============================================================
__global__ void __launch_bounds__(256)
mix_kernel(const float* __restrict__ x, float* __restrict__ out) {
    const int tok = blockIdx.x;
    const float* xr = x   + (size_t)tok * KDIM;
    float*       yr = out + (size_t)tok * KDIM;
    const float* hp = g_H + (size_t)tok * RROWS;

    float hres[16], hpre[4], hpost[4];
#pragma unroll
    for (int e = 0; e < 16; ++e) hres[e] = __ldg(hp + e);
#pragma unroll
    for (int s = 0; s < 4; ++s)  hpre[s]  = __ldg(hp + 16 + s);
#pragma unroll
    for (int s = 0; s < 4; ++s)  hpost[s] = __ldg(hp + 20 + s);

    const int col = threadIdx.x * 4;
    float4 xj[4];
#pragma unroll
    for (int j = 0; j < 4; ++j)
        xj[j] = *(const float4*)(xr + j * D4 + col);

    float4 bin;
    bin.x = hpre[0]*xj[0].x + hpre[1]*xj[1].x + hpre[2]*xj[2].x + hpre[3]*xj[3].x;
    bin.y = hpre[0]*xj[0].y + hpre[1]*xj[1].y + hpre[2]*xj[2].y + hpre[3]*xj[3].y;
    bin.z = hpre[0]*xj[0].z + hpre[1]*xj[1].z + hpre[2]*xj[2].z + hpre[3]*xj[3].z;
    bin.w = hpre[0]*xj[0].w + hpre[1]*xj[1].w + hpre[2]*xj[2].w + hpre[3]*xj[3].w;

#pragma unroll
    for (int i = 0; i < 4; ++i) {
        float4 o;
        o.x = hpost[i]*bin.x; o.y = hpost[i]*bin.y;
        o.z = hpost[i]*bin.z; o.w = hpost[i]*bin.w;
#pragma unroll
        for (int j = 0; j < 4; ++j) {
            float h = hres[i*4 + j];
            o.x += h * xj[j].x; o.y += h * xj[j].y;
            o.z += h * xj[j].z; o.w += h * xj[j].w;
        }
        *(float4*)(yr + i * D4 + col) = o;
    }
}

// ============================================================
// launch
// ============================================================
extern "C" void kernel_launch(void* const* d_in, const int* in_sizes, int n_in,
                              void* d_out, int out_size) {
    const float* residuals  = (const float*)d_in[0];
    const float* gamma      = (const float*)d_in[1];
    const float* w_res      = (const float*)d_in[2];
    const float* w_pre      = (const float*)d_in[3];
    const float* w_post     = (const float*)d_in[4];
    const float* beta_res   = (const float*)d_in[5];
    const float* beta_pre   = (const float*)d_in[6];
    const float* beta_post  = (const float*)d_in[7];
    const float* alpha_res  = (const float*)d_in[8];
    const float* alpha_pre  = (const float*)d_in[9];
    const float* alpha_post = (const float*)d_in[10];

    const int nt = in_sizes[0] / KDIM;   // B*T tokens (8192)

    prep_kernel<<<(RROWS * KDIM + 255) / 256, 256>>>(w_res, w_pre, w_post, gamma);
    dots_kernel<<<nt / 16, 256>>>(residuals);
    heads_kernel<<<(nt + 255) / 256, 256>>>(beta_res, beta_pre, beta_post,
                                            alpha_res, alpha_pre, alpha_post, nt);
    mix_kernel<<<nt, 256>>>(residuals, (float*)d_out);
}

// round 3
// speedup vs baseline: 1.4249x; 1.4249x over previous
#include <cuda_runtime.h>
#include <math.h>

#define S4     4
#define D4     1024
#define KDIM   4096      // S*D
#define RROWS  24        // 16 res + 4 pre + 4 post
#define MAXNT  8192      // B*T
#define CK     256       // k per chunk
#define NCH    (KDIM/CK) // 16

// -------- scratch (no cudaMalloc allowed) --------
__device__ float g_wg  [RROWS * KDIM];   // w * (1+gamma), row-major [r][k]
__device__ float g_dots[MAXNT * RROWS];  // raw dots per token
__device__ float g_ssq [MAXNT];          // sum of squares per token
__device__ float g_H   [MAXNT * RROWS];  // Hres[16], Hpre[4], Hpost[4]

typedef unsigned long long u64;

__device__ __forceinline__ u64 fma2(u64 a, u64 b, u64 c) {
    u64 d;
    asm("fma.rn.f32x2 %0, %1, %2, %3;" : "=l"(d) : "l"(a), "l"(b), "l"(c));
    return d;
}
__device__ __forceinline__ u64 add2(u64 a, u64 b) {
    u64 d;
    asm("add.rn.f32x2 %0, %1, %2;" : "=l"(d) : "l"(a), "l"(b));
    return d;
}
__device__ __forceinline__ u64 pack2(float lo, float hi) {
    u64 d;
    asm("mov.b64 %0, {%1, %2};" : "=l"(d) : "f"(lo), "f"(hi));
    return d;
}
__device__ __forceinline__ void unpack2(u64 a, float& lo, float& hi) {
    asm("mov.b64 {%0, %1}, %2;" : "=f"(lo), "=f"(hi) : "l"(a));
}
__device__ __forceinline__ void cpasync16(void* dst_smem, const void* src) {
    unsigned d = (unsigned)__cvta_generic_to_shared(dst_smem);
    asm volatile("cp.async.cg.shared.global [%0], [%1], 16;" :: "r"(d), "l"(src));
}

// ============================================================
// K0: fold gamma into concatenated weight matrix
// ============================================================
__global__ void prep_kernel(const float* __restrict__ w_res,
                            const float* __restrict__ w_pre,
                            const float* __restrict__ w_post,
                            const float* __restrict__ gamma) {
    int idx = blockIdx.x * blockDim.x + threadIdx.x;
    if (idx >= RROWS * KDIM) return;
    int r = idx >> 12;          // / 4096
    int k = idx & (KDIM - 1);
    float w;
    if (r < 16)      w = w_res [r * KDIM + k];
    else if (r < 20) w = w_pre [(r - 16) * KDIM + k];
    else             w = w_post[(r - 20) * KDIM + k];
    g_wg[idx] = w * (1.0f + gamma[k]);
}

// ============================================================
// K1: per-token sumsq + 24 raw dots.
// Block = 32 tokens, 256 threads (8 warps = 4 warp-pairs).
// warp-pair handles 8 tokens as 4 f32x2 lane-pairs; half 0 -> rows 0..11,
// half 1 -> rows 12..23. x staged in smem PRE-PACKED as token pairs;
// w chunk in smem. Double-buffered, cp.async for w, reg prefetch for x.
// ============================================================
__global__ void __launch_bounds__(256, 1)
dots_kernel(const float* __restrict__ x) {
    extern __shared__ __align__(16) char smem_raw[];
    float* sw = (float*)smem_raw;                       // [2][24*256]
    u64*   sx = (u64*)(smem_raw + 2 * RROWS * CK * 4);  // [2][16*256]

    const int tid  = threadIdx.x;
    const int lane = tid & 31;
    const int warp = tid >> 5;
    const int wp   = warp >> 1;        // 0..3 warp-pair
    const int half = warp & 1;         // row half
    const int tok_blk = blockIdx.x * 32;

    u64 acc[12][4];
#pragma unroll
    for (int r = 0; r < 12; ++r)
#pragma unroll
        for (int p = 0; p < 4; ++p) acc[r][p] = 0ull;
    u64 ssqp[4] = {0ull, 0ull, 0ull, 0ull};

    // ---- staging index precompute (4 x-items, 6 w-items per thread) ----
    // x item j: global item i = tid + 256*j; pair = i>>6 (0..15), k4 = i&63
    // w item j: f4 index f = tid + 256*j; row = f>>6, col4 = f&63

    // ---- prologue: stage chunk 0 into buf 0 ----
    {
#pragma unroll
        for (int j = 0; j < 6; ++j) {
            int f = tid + 256 * j;
            int row = f >> 6, col4 = f & 63;
            cpasync16(sw + row * CK + col4 * 4,
                      g_wg + row * KDIM + col4 * 4);
        }
#pragma unroll
        for (int j = 0; j < 4; ++j) {
            int i = tid + 256 * j;
            int pr = i >> 6, k4 = i & 63;
            const float* pa = x + (size_t)(tok_blk + 2 * pr) * KDIM + k4 * 4;
            float4 a = *(const float4*)pa;
            float4 b = *(const float4*)(pa + KDIM);
            ulonglong2 v0, v1;
            v0.x = pack2(a.x, b.x); v0.y = pack2(a.y, b.y);
            v1.x = pack2(a.z, b.z); v1.y = pack2(a.w, b.w);
            ((ulonglong2*)(sx + pr * CK + k4 * 4))[0] = v0;
            ((ulonglong2*)(sx + pr * CK + k4 * 4))[1] = v1;
        }
        asm volatile("cp.async.commit_group;");
        asm volatile("cp.async.wait_group 0;" ::: "memory");
    }
    __syncthreads();

    for (int c = 0; c < NCH; ++c) {
        const int buf  = c & 1;
        const int nbuf = buf ^ 1;
        float* swb = sw + buf * (RROWS * CK);
        u64*   sxb = sx + buf * (16 * CK);

        // prefetch next chunk: w via cp.async, x into registers
        float4 xa[4], xb[4];
        if (c + 1 < NCH) {
#pragma unroll
            for (int j = 0; j < 6; ++j) {
                int f = tid + 256 * j;
                int row = f >> 6, col4 = f & 63;
                cpasync16(sw + nbuf * (RROWS * CK) + row * CK + col4 * 4,
                          g_wg + row * KDIM + (c + 1) * CK + col4 * 4);
            }
            asm volatile("cp.async.commit_group;");
#pragma unroll
            for (int j = 0; j < 4; ++j) {
                int i = tid + 256 * j;
                int pr = i >> 6, k4 = i & 63;
                const float* pa = x + (size_t)(tok_blk + 2 * pr) * KDIM
                                    + (c + 1) * CK + k4 * 4;
                xa[j] = *(const float4*)pa;
                xb[j] = *(const float4*)(pa + KDIM);
            }
        }

        // ---- compute 4 its (64 k each, 2 k per lane) ----
#pragma unroll
        for (int it = 0; it < 4; ++it) {
            const int k0 = it * 64 + lane * 2;
            ulonglong2 xp[4];
#pragma unroll
            for (int p = 0; p < 4; ++p)
                xp[p] = *(const ulonglong2*)(sxb + (wp * 4 + p) * CK + k0);

            const float* wbase = swb + (half * 12) * CK + k0;
#pragma unroll
            for (int r = 0; r < 12; ++r) {
                float2 wv = *(const float2*)(wbase + r * CK);
                u64 W0 = pack2(wv.x, wv.x);
                u64 W1 = pack2(wv.y, wv.y);
#pragma unroll
                for (int p = 0; p < 4; ++p) {
                    acc[r][p] = fma2(W0, xp[p].x, acc[r][p]);
                    acc[r][p] = fma2(W1, xp[p].y, acc[r][p]);
                }
            }
            if (half == 0) {
#pragma unroll
                for (int p = 0; p < 4; ++p) {
                    ssqp[p] = fma2(xp[p].x, xp[p].x, ssqp[p]);
                    ssqp[p] = fma2(xp[p].y, xp[p].y, ssqp[p]);
                }
            }
        }

        // ---- store prefetched x (packed) into next buffer ----
        if (c + 1 < NCH) {
#pragma unroll
            for (int j = 0; j < 4; ++j) {
                int i = tid + 256 * j;
                int pr = i >> 6, k4 = i & 63;
                ulonglong2 v0, v1;
                v0.x = pack2(xa[j].x, xb[j].x); v0.y = pack2(xa[j].y, xb[j].y);
                v1.x = pack2(xa[j].z, xb[j].z); v1.y = pack2(xa[j].w, xb[j].w);
                u64* dst = sx + nbuf * (16 * CK) + pr * CK + k4 * 4;
                ((ulonglong2*)dst)[0] = v0;
                ((ulonglong2*)dst)[1] = v1;
            }
            asm volatile("cp.async.wait_group 0;" ::: "memory");
        }
        __syncthreads();
    }

    // ---- reduce across lanes and write ----
#pragma unroll
    for (int r = 0; r < 12; ++r) {
#pragma unroll
        for (int p = 0; p < 4; ++p) {
            u64 a = acc[r][p];
            a = add2(a, __shfl_down_sync(0xffffffffu, a, 16));
            a = add2(a, __shfl_down_sync(0xffffffffu, a, 8));
            a = add2(a, __shfl_down_sync(0xffffffffu, a, 4));
            a = add2(a, __shfl_down_sync(0xffffffffu, a, 2));
            a = add2(a, __shfl_down_sync(0xffffffffu, a, 1));
            if (lane == 0) {
                float lo, hi; unpack2(a, lo, hi);
                int ta = tok_blk + wp * 8 + 2 * p;
                int row = half * 12 + r;
                g_dots[(size_t)ta * RROWS + row]       = lo;
                g_dots[(size_t)(ta + 1) * RROWS + row] = hi;
            }
        }
    }
    if (half == 0) {
#pragma unroll
        for (int p = 0; p < 4; ++p) {
            u64 a = ssqp[p];
            a = add2(a, __shfl_down_sync(0xffffffffu, a, 16));
            a = add2(a, __shfl_down_sync(0xffffffffu, a, 8));
            a = add2(a, __shfl_down_sync(0xffffffffu, a, 4));
            a = add2(a, __shfl_down_sync(0xffffffffu, a, 2));
            a = add2(a, __shfl_down_sync(0xffffffffu, a, 1));
            if (lane == 0) {
                float lo, hi; unpack2(a, lo, hi);
                int ta = tok_blk + wp * 8 + 2 * p;
                g_ssq[ta]     = lo;
                g_ssq[ta + 1] = hi;
            }
        }
    }
}

// ============================================================
// K2: per-token heads (sinkhorn + softmax + sigmoid)
// ============================================================
__device__ __forceinline__ float lse4(float a, float b, float c, float d) {
    float m = fmaxf(fmaxf(a, b), fmaxf(c, d));
    float s = expf(a - m) + expf(b - m) + expf(c - m) + expf(d - m);
    return m + logf(s);
}

__global__ void heads_kernel(const float* __restrict__ beta_res,
                             const float* __restrict__ beta_pre,
                             const float* __restrict__ beta_post,
                             const float* __restrict__ alpha_res,
                             const float* __restrict__ alpha_pre,
                             const float* __restrict__ alpha_post,
                             int nt) {
    int tok = blockIdx.x * blockDim.x + threadIdx.x;
    if (tok >= nt) return;

    float rstd = 64.0f / fmaxf(sqrtf(g_ssq[tok]), 1e-12f);
    const float* dp = g_dots + (size_t)tok * RROWS;
    float ar = alpha_res[0]  * rstd;
    float ap = alpha_pre[0]  * rstd;
    float ao = alpha_post[0] * rstd;

    float Z[16];
#pragma unroll
    for (int e = 0; e < 16; ++e)
        Z[e] = (beta_res[e] + ar * dp[e]) * 20.0f;   // / tau, tau = 0.05

    float u[4] = {0.f, 0.f, 0.f, 0.f};
    float v[4] = {0.f, 0.f, 0.f, 0.f};
#pragma unroll 1
    for (int itn = 0; itn < 10; ++itn) {
#pragma unroll
        for (int i = 0; i < 4; ++i)
            u[i] = -lse4(Z[i*4+0] + v[0], Z[i*4+1] + v[1],
                         Z[i*4+2] + v[2], Z[i*4+3] + v[3]);
#pragma unroll
        for (int j = 0; j < 4; ++j)
            v[j] = -lse4(Z[0*4+j] + u[0], Z[1*4+j] + u[1],
                         Z[2*4+j] + u[2], Z[3*4+j] + u[3]);
    }

    float* hp = g_H + (size_t)tok * RROWS;
#pragma unroll
    for (int i = 0; i < 4; ++i)
#pragma unroll
        for (int j = 0; j < 4; ++j)
            hp[i*4+j] = expf(Z[i*4+j] + u[i] + v[j]);

    float p[4];
#pragma unroll
    for (int s = 0; s < 4; ++s) p[s] = beta_pre[s] + ap * dp[16 + s];
    float m = fmaxf(fmaxf(p[0], p[1]), fmaxf(p[2], p[3]));
    float e0 = expf(p[0]-m), e1 = expf(p[1]-m), e2 = expf(p[2]-m), e3 = expf(p[3]-m);
    float inv = 1.0f / (e0 + e1 + e2 + e3);
    hp[16] = e0*inv; hp[17] = e1*inv; hp[18] = e2*inv; hp[19] = e3*inv;

#pragma unroll
    for (int s = 0; s < 4; ++s) {
        float q = beta_post[s] + ao * dp[20 + s];
        hp[20 + s] = 2.0f / (1.0f + expf(-q));
    }
}

// ============================================================
// K3: out[i,d] = sum_j Hres[i][j] x[j,d] + Hpost[i] * sum_s Hpre[s] x[s,d]
// ============================================================
__global__ void __launch_bounds__(256)
mix_kernel(const float* __restrict__ x, float* __restrict__ out) {
    const int tok = blockIdx.x;
    const float* xr = x   + (size_t)tok * KDIM;
    float*       yr = out + (size_t)tok * KDIM;
    const float* hp = g_H + (size_t)tok * RROWS;

    float hres[16], hpre[4], hpost[4];
#pragma unroll
    for (int e = 0; e < 16; ++e) hres[e] = __ldg(hp + e);
#pragma unroll
    for (int s = 0; s < 4; ++s)  hpre[s]  = __ldg(hp + 16 + s);
#pragma unroll
    for (int s = 0; s < 4; ++s)  hpost[s] = __ldg(hp + 20 + s);

    const int col = threadIdx.x * 4;
    float4 xj[4];
#pragma unroll
    for (int j = 0; j < 4; ++j)
        xj[j] = __ldcs((const float4*)(xr + j * D4 + col));

    float4 bin;
    bin.x = hpre[0]*xj[0].x + hpre[1]*xj[1].x + hpre[2]*xj[2].x + hpre[3]*xj[3].x;
    bin.y = hpre[0]*xj[0].y + hpre[1]*xj[1].y + hpre[2]*xj[2].y + hpre[3]*xj[3].y;
    bin.z = hpre[0]*xj[0].z + hpre[1]*xj[1].z + hpre[2]*xj[2].z + hpre[3]*xj[3].z;
    bin.w = hpre[0]*xj[0].w + hpre[1]*xj[1].w + hpre[2]*xj[2].w + hpre[3]*xj[3].w;

#pragma unroll
    for (int i = 0; i < 4; ++i) {
        float4 o;
        o.x = hpost[i]*bin.x; o.y = hpost[i]*bin.y;
        o.z = hpost[i]*bin.z; o.w = hpost[i]*bin.w;
#pragma unroll
        for (int j = 0; j < 4; ++j) {
            float h = hres[i*4 + j];
            o.x += h * xj[j].x; o.y += h * xj[j].y;
            o.z += h * xj[j].z; o.w += h * xj[j].w;
        }
        __stcs((float4*)(yr + i * D4 + col), o);
    }
}

// ============================================================
// launch
// ============================================================
extern "C" void kernel_launch(void* const* d_in, const int* in_sizes, int n_in,
                              void* d_out, int out_size) {
    const float* residuals  = (const float*)d_in[0];
    const float* gamma      = (const float*)d_in[1];
    const float* w_res      = (const float*)d_in[2];
    const float* w_pre      = (const float*)d_in[3];
    const float* w_post     = (const float*)d_in[4];
    const float* beta_res   = (const float*)d_in[5];
    const float* beta_pre   = (const float*)d_in[6];
    const float* beta_post  = (const float*)d_in[7];
    const float* alpha_res  = (const float*)d_in[8];
    const float* alpha_pre  = (const float*)d_in[9];
    const float* alpha_post = (const float*)d_in[10];

    const int nt = in_sizes[0] / KDIM;   // B*T tokens (8192)

    const int smem_bytes = 2 * RROWS * CK * 4 + 2 * 16 * CK * 8;  // 112 KB
    static bool attr_set = false;
    if (!attr_set) {
        cudaFuncSetAttribute(dots_kernel,
                             cudaFuncAttributeMaxDynamicSharedMemorySize,
                             smem_bytes);
        attr_set = true;
    }

    prep_kernel<<<(RROWS * KDIM + 255) / 256, 256>>>(w_res, w_pre, w_post, gamma);
    dots_kernel<<<nt / 32, 256, smem_bytes>>>(residuals);
    heads_kernel<<<(nt + 255) / 256, 256>>>(beta_res, beta_pre, beta_post,
                                            alpha_res, alpha_pre, alpha_post, nt);
    mix_kernel<<<nt, 256>>>(residuals, (float*)d_out);
}